// round 7
// baseline (speedup 1.0000x reference)
#include <cuda_runtime.h>
#include <cuda_bf16.h>

// Sampler_51419348468365 — FINAL (R2 configuration, best measured: 6.400 us)
//
// Reference epilogue: out = stop_gradient(1 - y) + y. stop_gradient is
// identity on values, so out = (1 - y) + y == 1.0f up to <= ~1.2e-7 fp32
// rounding (y = softmax in (0,1)); tolerance is 1e-3. The entire
// gather/Gumbel/segment-softmax pipeline is value-dead; the optimal kernel
// writes constant 1.0f to all out_size floats.
//
// Exhaustively measured variants (fat loop / thin STG / single-wave MLP=8 /
// driver memset node / 512-wide blocks): all 6.40-6.62 us e2e, kernel
// 4.03-4.29 us — the graph-replay + launch floor. Store work itself is
// ~0.35 us of L2 traffic. This is the best-measured configuration:
// 256-thread blocks, 1024 CTAs, one predicated STG.128 per thread; tail
// (out_size % 4) handled by trailing threads (dead code for out_size = 2^20).

__global__ __launch_bounds__(256, 1)
void Sampler_fill_ones(float4* __restrict__ out4, int n4,
                       float* __restrict__ out_tail, int n_total) {
    int i = blockIdx.x * 256 + threadIdx.x;
    const float4 ones = make_float4(1.0f, 1.0f, 1.0f, 1.0f);
    if (i < n4) {
        out4[i] = ones;
    }
    int t = i - n4;  // >= 0 only for trailing threads
    if (t >= 0 && 4 * n4 + t < n_total) {
        out_tail[4 * n4 + t] = 1.0f;
    }
}

extern "C" void kernel_launch(void* const* d_in, const int* in_sizes, int n_in,
                              void* d_out, int out_size) {
    (void)d_in; (void)in_sizes; (void)n_in;
    float* out = (float*)d_out;
    int n4 = out_size / 4;                         // 262144
    int total_threads = n4 + (out_size - 4 * n4);  // + tail threads
    if (total_threads < 1) total_threads = 1;
    int blocks = (total_threads + 255) / 256;      // 1024 blocks for 2^20
    Sampler_fill_ones<<<blocks, 256>>>((float4*)out, n4, out, out_size);
}